// round 3
// baseline (speedup 1.0000x reference)
#include <cuda_runtime.h>
#include <cstdint>

// ---------------------------------------------------------------------------
// VolterraGraphConvLayer on GB300 (sm_103, legacy mma.sync path — 'a' features
// are unavailable in this build pipeline).
//   M[p] = A[p] @ X          (P=3, N=8192, D=256, K=8192)
//   out  = relu(X@W0^T + S1@W1^T + S2@W2^T + (b0+3b1+6b2))
// X pre-rounded to tf32(rna) + transposed into g_Xt. A fed raw (HW truncation),
// compensated by CF on M. gemm1: BM=64 BN=256 BK=64, 384 CTAs (3 even waves).
// ---------------------------------------------------------------------------

#define N_NODES 8192
#define DIM     256
#define NPOW    3
#define CF      1.000169f   // E[tf32-truncation loss] = 2^-12 * ln2

__device__ __align__(1024) float g_M[(size_t)NPOW * N_NODES * DIM];   // 24 MB
__device__ __align__(1024) float g_Xt[(size_t)DIM * N_NODES];          // 8 MB [feat][node], tf32-rna

// ---------------- PTX helpers ----------------
__device__ __forceinline__ uint32_t smem_u32(const void* p) {
    return (uint32_t)__cvta_generic_to_shared(p);
}
__device__ __forceinline__ void cp_async16(uint32_t dst, const void* src) {
    asm volatile("cp.async.cg.shared.global [%0], [%1], 16;\n" :: "r"(dst), "l"(src));
}
__device__ __forceinline__ void cp_commit() { asm volatile("cp.async.commit_group;\n"); }
template <int N> __device__ __forceinline__ void cp_wait() {
    asm volatile("cp.async.wait_group %0;\n" :: "n"(N));
}
__device__ __forceinline__ uint32_t f2tf32(float x) {
    uint32_t r; asm("cvt.rna.tf32.f32 %0, %1;\n" : "=r"(r) : "f"(x)); return r;
}
__device__ __forceinline__ void mma_tf32(float c[4],
                                         uint32_t a0, uint32_t a1, uint32_t a2, uint32_t a3,
                                         uint32_t b0, uint32_t b1) {
    asm volatile(
        "mma.sync.aligned.m16n8k8.row.col.f32.tf32.tf32.f32 "
        "{%0,%1,%2,%3}, {%4,%5,%6,%7}, {%8,%9}, {%0,%1,%2,%3};\n"
        : "+f"(c[0]), "+f"(c[1]), "+f"(c[2]), "+f"(c[3])
        : "r"(a0), "r"(a1), "r"(a2), "r"(a3), "r"(b0), "r"(b1));
}

// ---------------------------------------------------------------------------
// Kernel 0: g_Xt[feat][node] = tf32_rna(X[node][feat])
// ---------------------------------------------------------------------------
__global__ void __launch_bounds__(256)
prep_xt(const float* __restrict__ X) {
    __shared__ float t[32][33];
    const int n0 = blockIdx.x * 32;
    const int f0 = blockIdx.y * 32;
    const int tx = threadIdx.x, ty = threadIdx.y;
#pragma unroll
    for (int j = 0; j < 32; j += 8)
        t[ty + j][tx] = __uint_as_float(f2tf32(X[(size_t)(n0 + ty + j) * DIM + f0 + tx]));
    __syncthreads();
#pragma unroll
    for (int j = 0; j < 32; j += 8)
        g_Xt[(size_t)(f0 + ty + j) * N_NODES + n0 + tx] = t[tx][ty + j];
}

// ---------------------------------------------------------------------------
// Kernel 1:  M[p] = CF * (A[p] @ X)   — legacy tf32 mma, no cvt in hot loop
// BM=64, BN=256, BK=64, 512 threads (4 row-groups x 4 col-groups of warps),
// 2-stage cp.async ring. grid = 3 * 128 = 384 CTAs.
// ---------------------------------------------------------------------------
#define G1_BM   64
#define G1_BK   64
#define PAD_STRIDE 68                                  // 64 + 4 pad
#define A_STAGE   (G1_BM * PAD_STRIDE)                 // 4352 floats
#define X_STAGE   (DIM   * PAD_STRIDE)                 // 17408 floats
#define STAGE_FLOATS (A_STAGE + X_STAGE)               // 21760
#define G1_SMEM   (2 * STAGE_FLOATS * 4)               // 174080 bytes

__global__ void __launch_bounds__(512, 1)
volterra_gemm1(const float* __restrict__ A) {
    extern __shared__ float smem[];

    const int tid  = threadIdx.x;
    const int wid  = tid >> 5;
    const int lane = tid & 31;
    const int p       = blockIdx.x >> 7;          // /128
    const int rowTile = blockIdx.x & 127;
    const int row0    = rowTile * G1_BM;
    const float* Ap   = A + (size_t)p * N_NODES * N_NODES;

    const int warpRow = (wid >> 2) * 16;          // 4 groups of 16 rows
    const int warpCol = (wid & 3) * 64;           // 4 groups of 64 cols

    float acc[8][4];
#pragma unroll
    for (int nt = 0; nt < 8; nt++)
#pragma unroll
        for (int i = 0; i < 4; i++) acc[nt][i] = 0.f;

    const uint32_t sbase = smem_u32(smem);

    auto issue = [&](int kt) {
        const int stg = kt & 1;
        const uint32_t sa = sbase + stg * STAGE_FLOATS * 4;
        const uint32_t sx = sa + A_STAGE * 4;
        const int k0 = kt * G1_BK;
        // A tile: 64 x 64 floats = 1024 float4, 2 per thread
#pragma unroll
        for (int i = 0; i < 2; i++) {
            int idx = tid + i * 512;
            int r = idx >> 4, c4 = idx & 15;
            cp_async16(sa + (uint32_t)(r * PAD_STRIDE + c4 * 4) * 4,
                       Ap + (size_t)(row0 + r) * N_NODES + k0 + c4 * 4);
        }
        // X tile: 256 x 64 floats = 4096 float4, 8 per thread  (g_Xt rows)
#pragma unroll
        for (int i = 0; i < 8; i++) {
            int idx = tid + i * 512;
            int n = idx >> 4, c4 = idx & 15;
            cp_async16(sx + (uint32_t)(n * PAD_STRIDE + c4 * 4) * 4,
                       g_Xt + (size_t)n * N_NODES + k0 + c4 * 4);
        }
        cp_commit();
    };

    issue(0);

    const int NT = N_NODES / G1_BK;    // 128
    for (int kt = 0; kt < NT; kt++) {
        if (kt + 1 < NT) { issue(kt + 1); cp_wait<1>(); }
        else             { cp_wait<0>(); }
        __syncthreads();

        const float* as = smem + (kt & 1) * STAGE_FLOATS;
        const float* xs = as + A_STAGE;

        const int ar = warpRow + (lane >> 2);
        const int al = lane & 3;

#pragma unroll
        for (int k8 = 0; k8 < 8; k8++) {
            const int kb = k8 * 8;
            // A fragment (raw bits; HW truncates to tf32, compensated by CF)
            uint32_t a0 = __float_as_uint(as[ar * PAD_STRIDE + kb + al]);
            uint32_t a1 = __float_as_uint(as[(ar + 8) * PAD_STRIDE + kb + al]);
            uint32_t a2 = __float_as_uint(as[ar * PAD_STRIDE + kb + al + 4]);
            uint32_t a3 = __float_as_uint(as[(ar + 8) * PAD_STRIDE + kb + al + 4]);
#pragma unroll
            for (int nt = 0; nt < 8; nt++) {
                int n = warpCol + nt * 8 + (lane >> 2);
                uint32_t b0 = __float_as_uint(xs[n * PAD_STRIDE + kb + al]);
                uint32_t b1 = __float_as_uint(xs[n * PAD_STRIDE + kb + al + 4]);
                mma_tf32(acc[nt], a0, a1, a2, a3, b0, b1);
            }
        }
        __syncthreads();
    }

    // ---- epilogue: CF scale + store ----
    float* Mout = g_M + (size_t)p * N_NODES * DIM;
    const int r0 = row0 + warpRow + (lane >> 2);
#pragma unroll
    for (int nt = 0; nt < 8; nt++) {
        int c = warpCol + nt * 8 + 2 * (lane & 3);
        float2 v0 = make_float2(CF * acc[nt][0], CF * acc[nt][1]);
        float2 v1 = make_float2(CF * acc[nt][2], CF * acc[nt][3]);
        *(float2*)&Mout[(size_t)r0 * DIM + c]       = v0;
        *(float2*)&Mout[(size_t)(r0 + 8) * DIM + c] = v1;
    }
}

// ---------------------------------------------------------------------------
// Kernel 2:  out = relu( [X | S1 | S2] @ [W0 | W1 | W2]^T + bias )
// BM=64, BN=128 (2 column halves), grid (128, 2), 256 threads.
// ---------------------------------------------------------------------------
#define TS_STRIDE 36
__global__ void __launch_bounds__(256)
volterra_gemm2(const float* __restrict__ X, const float* __restrict__ W,
               const float* __restrict__ bvec, float* __restrict__ out) {
    __shared__ float Ts[64][TS_STRIDE];
    __shared__ float Ws[128][TS_STRIDE];

    const int row0 = blockIdx.x * 64;
    const int col0 = blockIdx.y * 128;
    const int tid  = threadIdx.x;
    const int wid  = tid >> 5;
    const int lane = tid & 31;
    const int warpRow = (wid >> 2) * 32;   // 2 groups of 32 rows
    const int warpCol = (wid & 3) * 32;    // 4 groups of 32 cols

    float acc[2][4][4];
#pragma unroll
    for (int mt = 0; mt < 2; mt++)
#pragma unroll
        for (int nt = 0; nt < 4; nt++)
#pragma unroll
            for (int i = 0; i < 4; i++) acc[mt][nt][i] = 0.f;

    const size_t MSZ = (size_t)N_NODES * DIM;

    for (int kc = 0; kc < 24; kc++) {
        const int r  = kc >> 3;
        const int k0 = (kc & 7) * 32;

        // T chunk: 64 x 32 = 512 float4, 2 per thread
#pragma unroll
        for (int i = 0; i < 2; i++) {
            int idx = tid + i * 256;
            int rr = idx >> 3, c4 = idx & 7;
            size_t g = (size_t)(row0 + rr) * DIM + k0 + c4 * 4;
            float4 v;
            if (r == 0) {
                v = *(const float4*)&X[g];
            } else {
                float4 m0 = *(const float4*)&g_M[g];
                float4 m1 = *(const float4*)&g_M[MSZ + g];
                float4 m2 = *(const float4*)&g_M[2 * MSZ + g];
                if (r == 1) {
                    v.x = m0.x + m1.x + m2.x;  v.y = m0.y + m1.y + m2.y;
                    v.z = m0.z + m1.z + m2.z;  v.w = m0.w + m1.w + m2.w;
                } else {
                    float s, q;
                    s = m0.x + m1.x + m2.x; q = m0.x*m0.x + m1.x*m1.x + m2.x*m2.x; v.x = 0.5f*(s*s + q);
                    s = m0.y + m1.y + m2.y; q = m0.y*m0.y + m1.y*m1.y + m2.y*m2.y; v.y = 0.5f*(s*s + q);
                    s = m0.z + m1.z + m2.z; q = m0.z*m0.z + m1.z*m1.z + m2.z*m2.z; v.z = 0.5f*(s*s + q);
                    s = m0.w + m1.w + m2.w; q = m0.w*m0.w + m1.w*m1.w + m2.w*m2.w; v.w = 0.5f*(s*s + q);
                }
            }
            *(float4*)&Ts[rr][c4 * 4] = v;
        }
        // W_r chunk: 128 x 32 = 1024 float4, 4 per thread
        const float* Wr = W + (size_t)r * DIM * DIM;
#pragma unroll
        for (int i = 0; i < 4; i++) {
            int idx = tid + i * 256;
            int d = idx >> 3, c4 = idx & 7;
            *(float4*)&Ws[d][c4 * 4] = *(const float4*)&Wr[(size_t)(col0 + d) * DIM + k0 + c4 * 4];
        }
        __syncthreads();

#pragma unroll
        for (int k8 = 0; k8 < 4; k8++) {
            const int kb = k8 * 8;
            uint32_t af[2][4];
#pragma unroll
            for (int mt = 0; mt < 2; mt++) {
                int rr = warpRow + mt * 16 + (lane >> 2);
                int c = kb + (lane & 3);
                af[mt][0] = f2tf32(Ts[rr][c]);
                af[mt][1] = f2tf32(Ts[rr + 8][c]);
                af[mt][2] = f2tf32(Ts[rr][c + 4]);
                af[mt][3] = f2tf32(Ts[rr + 8][c + 4]);
            }
#pragma unroll
            for (int nt = 0; nt < 4; nt++) {
                int d = warpCol + nt * 8 + (lane >> 2);
                int k = kb + (lane & 3);
                uint32_t b0 = f2tf32(Ws[d][k]);
                uint32_t b1 = f2tf32(Ws[d][k + 4]);
                mma_tf32(acc[0][nt], af[0][0], af[0][1], af[0][2], af[0][3], b0, b1);
                mma_tf32(acc[1][nt], af[1][0], af[1][1], af[1][2], af[1][3], b0, b1);
            }
        }
        __syncthreads();
    }

#pragma unroll
    for (int nt = 0; nt < 4; nt++) {
        int c  = col0 + warpCol + nt * 8 + 2 * (lane & 3);
        float bias0 = bvec[c]     + 3.f * bvec[DIM + c]     + 6.f * bvec[2 * DIM + c];
        float bias1 = bvec[c + 1] + 3.f * bvec[DIM + c + 1] + 6.f * bvec[2 * DIM + c + 1];
#pragma unroll
        for (int mt = 0; mt < 2; mt++) {
            int rr = row0 + warpRow + mt * 16 + (lane >> 2);
            float2 v0 = make_float2(fmaxf(acc[mt][nt][0] + bias0, 0.f),
                                    fmaxf(acc[mt][nt][1] + bias1, 0.f));
            float2 v1 = make_float2(fmaxf(acc[mt][nt][2] + bias0, 0.f),
                                    fmaxf(acc[mt][nt][3] + bias1, 0.f));
            *(float2*)&out[(size_t)rr * DIM + c]       = v0;
            *(float2*)&out[(size_t)(rr + 8) * DIM + c] = v1;
        }
    }
}

// ---------------------------------------------------------------------------
extern "C" void kernel_launch(void* const* d_in, const int* in_sizes, int n_in,
                              void* d_out, int out_size) {
    const float *X = nullptr, *A = nullptr, *W = nullptr, *b = nullptr;
    for (int i = 0; i < n_in; i++) {
        long long s = in_sizes[i];
        if      (s == (long long)N_NODES * DIM)            X = (const float*)d_in[i];
        else if (s == (long long)NPOW * N_NODES * N_NODES) A = (const float*)d_in[i];
        else if (s == (long long)NPOW * DIM * DIM)         W = (const float*)d_in[i];
        else if (s == (long long)NPOW * DIM)               b = (const float*)d_in[i];
    }

    cudaFuncSetAttribute(volterra_gemm1,
                         cudaFuncAttributeMaxDynamicSharedMemorySize, G1_SMEM);

    prep_xt<<<dim3(N_NODES / 32, DIM / 32), dim3(32, 8)>>>(X);
    volterra_gemm1<<<NPOW * (N_NODES / G1_BM), 512, G1_SMEM>>>(A);
    volterra_gemm2<<<dim3(N_NODES / 64, 2), 256>>>(X, W, b, (float*)d_out);
}

// round 8
// speedup vs baseline: 2.1960x; 2.1960x over previous
#include <cuda_runtime.h>
#include <cuda_fp16.h>
#include <cstdint>

// ---------------------------------------------------------------------------
// VolterraGraphConvLayer on GB300 (sm_103 non-'a': legacy mma.sync only).
//   gemm1: M[p] = A[p] @ X   via fp16 mma.m16n8k16 (f32 accum),
//          persistent 148 CTAs, 384 tiles of 64x256, K=8192, BK=64.
//   gemm2: out = relu([X|S1|S2] @ [W0|W1|W2]^T + bias)  via tf32 mma.
// X pre-converted (rna) to transposed fp16 g_Xh with k-interleave so B
// fragments are one conflict-free LDS.64; A converted f32->fp16 after LDG.
// (Resubmission of Round-4 design: container-level infra failure, kernel
//  audited clean — fragment maps, bank phases, pipeline syncs, bounds.)
// ---------------------------------------------------------------------------

#define N_NODES 8192
#define DIM     256
#define NPOW    3

__device__ __align__(1024) float  g_M [(size_t)NPOW * N_NODES * DIM];  // 24 MB
__device__ __align__(1024) __half g_Xh[(size_t)DIM * N_NODES];          // 4 MB [feat][node-perm]

// ---------------- PTX helpers ----------------
__device__ __forceinline__ uint32_t smem_u32(const void* p) {
    return (uint32_t)__cvta_generic_to_shared(p);
}
__device__ __forceinline__ void cp_async16(uint32_t dst, const void* src) {
    asm volatile("cp.async.cg.shared.global [%0], [%1], 16;\n" :: "r"(dst), "l"(src));
}
__device__ __forceinline__ void cp_commit() { asm volatile("cp.async.commit_group;\n"); }
template <int N> __device__ __forceinline__ void cp_wait() {
    asm volatile("cp.async.wait_group %0;\n" :: "n"(N));
}
__device__ __forceinline__ uint32_t f2tf32(float x) {
    uint32_t r; asm("cvt.rna.tf32.f32 %0, %1;\n" : "=r"(r) : "f"(x)); return r;
}
__device__ __forceinline__ uint32_t lds32(uint32_t a) {
    uint32_t r; asm volatile("ld.shared.b32 %0, [%1];" : "=r"(r) : "r"(a)); return r;
}
__device__ __forceinline__ void lds64(uint32_t& x, uint32_t& y, uint32_t a) {
    asm volatile("ld.shared.v2.b32 {%0,%1}, [%2];" : "=r"(x), "=r"(y) : "r"(a));
}
__device__ __forceinline__ void sts64(uint32_t a, uint32_t x, uint32_t y) {
    asm volatile("st.shared.v2.b32 [%0], {%1,%2};" :: "r"(a), "r"(x), "r"(y));
}
__device__ __forceinline__ void mma_f16(float c[4],
                                        uint32_t a0, uint32_t a1, uint32_t a2, uint32_t a3,
                                        uint32_t b0, uint32_t b1) {
    asm volatile(
        "mma.sync.aligned.m16n8k16.row.col.f32.f16.f16.f32 "
        "{%0,%1,%2,%3}, {%4,%5,%6,%7}, {%8,%9}, {%0,%1,%2,%3};\n"
        : "+f"(c[0]), "+f"(c[1]), "+f"(c[2]), "+f"(c[3])
        : "r"(a0), "r"(a1), "r"(a2), "r"(a3), "r"(b0), "r"(b1));
}
__device__ __forceinline__ void mma_tf32(float c[4],
                                         uint32_t a0, uint32_t a1, uint32_t a2, uint32_t a3,
                                         uint32_t b0, uint32_t b1) {
    asm volatile(
        "mma.sync.aligned.m16n8k8.row.col.f32.tf32.tf32.f32 "
        "{%0,%1,%2,%3}, {%4,%5,%6,%7}, {%8,%9}, {%0,%1,%2,%3};\n"
        : "+f"(c[0]), "+f"(c[1]), "+f"(c[2]), "+f"(c[3])
        : "r"(a0), "r"(a1), "r"(a2), "r"(a3), "r"(b0), "r"(b1));
}
__device__ __forceinline__ uint32_t h2u(__half2 h) {
    return *reinterpret_cast<uint32_t*>(&h);
}

// k-within-16 interleave: positions 4t..4t+3 hold original k {2t,2t+1,2t+8,2t+9}
__device__ __forceinline__ int hperm(int k) {
    return ((k & 7) >> 1) * 4 + ((k >> 3) & 1) * 2 + (k & 1);
}

// ---------------------------------------------------------------------------
// Kernel 0: g_Xh[feat][perm(node)] = fp16_rna(X[node][feat])
// ---------------------------------------------------------------------------
__global__ void __launch_bounds__(256)
prep_xh(const float* __restrict__ X) {
    __shared__ float t[32][33];
    const int n0 = blockIdx.x * 32;
    const int f0 = blockIdx.y * 32;
    const int tx = threadIdx.x, ty = threadIdx.y;
#pragma unroll
    for (int j = 0; j < 32; j += 8)
        t[ty + j][tx] = X[(size_t)(n0 + ty + j) * DIM + f0 + tx];
    __syncthreads();
    const int node = n0 + tx;
    const int ndst = (node & ~15) + hperm(node & 15);
#pragma unroll
    for (int j = 0; j < 32; j += 8)
        g_Xh[(size_t)(f0 + ty + j) * N_NODES + ndst] = __float2half_rn(t[tx][ty + j]);
}

// ---------------------------------------------------------------------------
// Kernel 1: persistent fp16 GEMM.  Tile 64x256, BK=64, NT=128, 256 threads.
// smem: A 2 stages x 64 rows x 144B  |  B 3 stages x 256 rows x 160B
// ---------------------------------------------------------------------------
#define A_ROWB   144
#define B_ROWB   160
#define A_STAGEB (64 * A_ROWB)        // 9216
#define B_STAGEB (256 * B_ROWB)       // 40960
#define B_BASE   (2 * A_STAGEB)       // 18432
#define G1_SMEM  (B_BASE + 3 * B_STAGEB + 1024)   // 142336
#define NT       128
#define TILES    (NPOW * (N_NODES / 64))          // 384
#define GRID1    148

__global__ void __launch_bounds__(256, 1)
volterra_gemm1(const float* __restrict__ A) {
    extern __shared__ char dsm[];
    const uint32_t base = (smem_u32(dsm) + 1023) & ~1023u;

    const int tid  = threadIdx.x;
    const int wid  = tid >> 5;
    const int lane = tid & 31;
    const int g    = lane >> 2;
    const int tq   = lane & 3;
    const int rw0  = (wid >> 2) * 32;     // 2 row groups of 32
    const int cw0  = (wid & 3) * 64;      // 4 col groups of 64

    const int lr[4] = { (tid + 0) >> 4, (tid + 256) >> 4, (tid + 512) >> 4, (tid + 768) >> 4 };
    const int lk    = (tid & 15) * 4;

    const uint32_t aFrag = base + (uint32_t)(rw0 + g) * A_ROWB + tq * 4;
    const uint32_t bFrag = base + B_BASE + (uint32_t)(cw0 + g) * B_ROWB + tq * 8;
    const uint32_t aStsBase = base;
    const uint32_t bCpBase  = base + B_BASE;

    for (int t = blockIdx.x; t < TILES; t += GRID1) {
        const int p    = t >> 7;
        const int row0 = (t & 127) * 64;
        const float* Ap = A + (size_t)p * N_NODES * N_NODES;

        float acc[2][8][4];
#pragma unroll
        for (int mt = 0; mt < 2; mt++)
#pragma unroll
            for (int nt = 0; nt < 8; nt++)
#pragma unroll
                for (int i = 0; i < 4; i++) acc[mt][nt][i] = 0.f;

        float4 buf[2][4];

        auto ldgA = [&](int kt, int which) {
            const int k0 = kt * 64;
#pragma unroll
            for (int i = 0; i < 4; i++)
                buf[which][i] = *(const float4*)(Ap + (size_t)(row0 + lr[i]) * N_NODES + k0 + lk);
        };
        auto stsA = [&](int kt, int which) {
            const uint32_t sa = aStsBase + (kt & 1) * A_STAGEB;
#pragma unroll
            for (int i = 0; i < 4; i++) {
                float4 v = buf[which][i];
                uint32_t u0 = h2u(__floats2half2_rn(v.x, v.y));
                uint32_t u1 = h2u(__floats2half2_rn(v.z, v.w));
                sts64(sa + (uint32_t)lr[i] * A_ROWB + (uint32_t)lk * 2, u0, u1);
            }
        };
        auto cpB = [&](int kt) {
            const uint32_t sb = bCpBase + (kt % 3) * B_STAGEB;
            const int k0 = kt * 64;
#pragma unroll
            for (int i = 0; i < 8; i++) {
                int idx = tid + i * 256;
                int n = idx >> 3, c = idx & 7;
                cp_async16(sb + (uint32_t)n * B_ROWB + c * 16,
                           g_Xh + (size_t)n * N_NODES + k0 + c * 8);
            }
            cp_commit();
        };

        ldgA(0, 0); ldgA(1, 1);
        cpB(0); cpB(1);
        stsA(0, 0);

        for (int kt = 0; kt < NT; kt++) {
            if (kt < NT - 2) cp_wait<1>(); else cp_wait<0>();
            __syncthreads();

            if (kt + 2 < NT) { cpB(kt + 2); ldgA(kt + 2, kt & 1); }
            if (kt + 1 < NT) stsA(kt + 1, (kt + 1) & 1);

            const uint32_t aS = aFrag + (kt & 1) * A_STAGEB;
            const uint32_t bS = bFrag + (kt % 3) * B_STAGEB;
#pragma unroll
            for (int k16 = 0; k16 < 4; k16++) {
                const uint32_t off = k16 * 32;
                uint32_t a0a = lds32(aS + off);
                uint32_t a1a = lds32(aS + off + 8 * A_ROWB);
                uint32_t a2a = lds32(aS + off + 16);
                uint32_t a3a = lds32(aS + off + 8 * A_ROWB + 16);
                uint32_t a0b = lds32(aS + off + 16 * A_ROWB);
                uint32_t a1b = lds32(aS + off + 24 * A_ROWB);
                uint32_t a2b = lds32(aS + off + 16 * A_ROWB + 16);
                uint32_t a3b = lds32(aS + off + 24 * A_ROWB + 16);
                uint32_t b0[8], b1[8];
#pragma unroll
                for (int nt = 0; nt < 8; nt++)
                    lds64(b0[nt], b1[nt], bS + nt * 8 * B_ROWB + off);
#pragma unroll
                for (int nt = 0; nt < 8; nt++) {
                    mma_f16(acc[0][nt], a0a, a1a, a2a, a3a, b0[nt], b1[nt]);
                    mma_f16(acc[1][nt], a0b, a1b, a2b, a3b, b0[nt], b1[nt]);
                }
            }
        }
        __syncthreads();

        float* Mo = g_M + (size_t)p * N_NODES * DIM;
#pragma unroll
        for (int mt = 0; mt < 2; mt++) {
            const int r = row0 + rw0 + mt * 16 + g;
#pragma unroll
            for (int nt = 0; nt < 8; nt++) {
                const int c = cw0 + nt * 8 + 2 * tq;
                *(float2*)&Mo[(size_t)r * DIM + c] =
                    make_float2(acc[mt][nt][0], acc[mt][nt][1]);
                *(float2*)&Mo[(size_t)(r + 8) * DIM + c] =
                    make_float2(acc[mt][nt][2], acc[mt][nt][3]);
            }
        }
    }
}

// ---------------------------------------------------------------------------
// Kernel 2:  out = relu( [X | S1 | S2] @ [W0 | W1 | W2]^T + bias )   (tf32)
// ---------------------------------------------------------------------------
#define TS_STRIDE 36
__global__ void __launch_bounds__(256)
volterra_gemm2(const float* __restrict__ X, const float* __restrict__ W,
               const float* __restrict__ bvec, float* __restrict__ out) {
    __shared__ float Ts[64][TS_STRIDE];
    __shared__ float Ws[128][TS_STRIDE];

    const int row0 = blockIdx.x * 64;
    const int col0 = blockIdx.y * 128;
    const int tid  = threadIdx.x;
    const int wid  = tid >> 5;
    const int lane = tid & 31;
    const int warpRow = (wid >> 2) * 32;
    const int warpCol = (wid & 3) * 32;

    float acc[2][4][4];
#pragma unroll
    for (int mt = 0; mt < 2; mt++)
#pragma unroll
        for (int nt = 0; nt < 4; nt++)
#pragma unroll
            for (int i = 0; i < 4; i++) acc[mt][nt][i] = 0.f;

    const size_t MSZ = (size_t)N_NODES * DIM;

    for (int kc = 0; kc < 24; kc++) {
        const int r  = kc >> 3;
        const int k0 = (kc & 7) * 32;

#pragma unroll
        for (int i = 0; i < 2; i++) {
            int idx = tid + i * 256;
            int rr = idx >> 3, c4 = idx & 7;
            size_t gidx = (size_t)(row0 + rr) * DIM + k0 + c4 * 4;
            float4 v;
            if (r == 0) {
                v = *(const float4*)&X[gidx];
            } else {
                float4 m0 = *(const float4*)&g_M[gidx];
                float4 m1 = *(const float4*)&g_M[MSZ + gidx];
                float4 m2 = *(const float4*)&g_M[2 * MSZ + gidx];
                if (r == 1) {
                    v.x = m0.x + m1.x + m2.x;  v.y = m0.y + m1.y + m2.y;
                    v.z = m0.z + m1.z + m2.z;  v.w = m0.w + m1.w + m2.w;
                } else {
                    float s, q;
                    s = m0.x + m1.x + m2.x; q = m0.x*m0.x + m1.x*m1.x + m2.x*m2.x; v.x = 0.5f*(s*s + q);
                    s = m0.y + m1.y + m2.y; q = m0.y*m0.y + m1.y*m1.y + m2.y*m2.y; v.y = 0.5f*(s*s + q);
                    s = m0.z + m1.z + m2.z; q = m0.z*m0.z + m1.z*m1.z + m2.z*m2.z; v.z = 0.5f*(s*s + q);
                    s = m0.w + m1.w + m2.w; q = m0.w*m0.w + m1.w*m1.w + m2.w*m2.w; v.w = 0.5f*(s*s + q);
                }
            }
            *(float4*)&Ts[rr][c4 * 4] = v;
        }
        const float* Wr = W + (size_t)r * DIM * DIM;
#pragma unroll
        for (int i = 0; i < 4; i++) {
            int idx = tid + i * 256;
            int d = idx >> 3, c4 = idx & 7;
            *(float4*)&Ws[d][c4 * 4] = *(const float4*)&Wr[(size_t)(col0 + d) * DIM + k0 + c4 * 4];
        }
        __syncthreads();

#pragma unroll
        for (int k8 = 0; k8 < 4; k8++) {
            const int kb = k8 * 8;
            uint32_t af[2][4];
#pragma unroll
            for (int mt = 0; mt < 2; mt++) {
                int rr = warpRow + mt * 16 + (lane >> 2);
                int c = kb + (lane & 3);
                af[mt][0] = f2tf32(Ts[rr][c]);
                af[mt][1] = f2tf32(Ts[rr + 8][c]);
                af[mt][2] = f2tf32(Ts[rr][c + 4]);
                af[mt][3] = f2tf32(Ts[rr + 8][c + 4]);
            }
#pragma unroll
            for (int nt = 0; nt < 4; nt++) {
                int d = warpCol + nt * 8 + (lane >> 2);
                int k = kb + (lane & 3);
                uint32_t b0 = f2tf32(Ws[d][k]);
                uint32_t b1 = f2tf32(Ws[d][k + 4]);
                mma_tf32(acc[0][nt], af[0][0], af[0][1], af[0][2], af[0][3], b0, b1);
                mma_tf32(acc[1][nt], af[1][0], af[1][1], af[1][2], af[1][3], b0, b1);
            }
        }
        __syncthreads();
    }

#pragma unroll
    for (int nt = 0; nt < 4; nt++) {
        int c  = col0 + warpCol + nt * 8 + 2 * (lane & 3);
        float bias0 = bvec[c]     + 3.f * bvec[DIM + c]     + 6.f * bvec[2 * DIM + c];
        float bias1 = bvec[c + 1] + 3.f * bvec[DIM + c + 1] + 6.f * bvec[2 * DIM + c + 1];
#pragma unroll
        for (int mt = 0; mt < 2; mt++) {
            int rr = row0 + warpRow + mt * 16 + (lane >> 2);
            float2 v0 = make_float2(fmaxf(acc[mt][nt][0] + bias0, 0.f),
                                    fmaxf(acc[mt][nt][1] + bias1, 0.f));
            float2 v1 = make_float2(fmaxf(acc[mt][nt][2] + bias0, 0.f),
                                    fmaxf(acc[mt][nt][3] + bias1, 0.f));
            *(float2*)&out[(size_t)rr * DIM + c]       = v0;
            *(float2*)&out[(size_t)(rr + 8) * DIM + c] = v1;
        }
    }
}

// ---------------------------------------------------------------------------
extern "C" void kernel_launch(void* const* d_in, const int* in_sizes, int n_in,
                              void* d_out, int out_size) {
    const float *X = nullptr, *A = nullptr, *W = nullptr, *b = nullptr;
    for (int i = 0; i < n_in; i++) {
        long long s = in_sizes[i];
        if      (s == (long long)N_NODES * DIM)            X = (const float*)d_in[i];
        else if (s == (long long)NPOW * N_NODES * N_NODES) A = (const float*)d_in[i];
        else if (s == (long long)NPOW * DIM * DIM)         W = (const float*)d_in[i];
        else if (s == (long long)NPOW * DIM)               b = (const float*)d_in[i];
    }

    cudaFuncSetAttribute(volterra_gemm1,
                         cudaFuncAttributeMaxDynamicSharedMemorySize, G1_SMEM);

    prep_xh<<<dim3(N_NODES / 32, DIM / 32), dim3(32, 8)>>>(X);
    volterra_gemm1<<<GRID1, 256, G1_SMEM>>>(A);
    volterra_gemm2<<<dim3(N_NODES / 64, 2), 256>>>(X, W, b, (float*)d_out);
}

// round 11
// speedup vs baseline: 3.2560x; 1.4827x over previous
#include <cuda_runtime.h>
#include <cuda_fp16.h>
#include <cstdint>

// ---------------------------------------------------------------------------
// VolterraGraphConvLayer on GB300 (sm_103 non-'a': legacy mma.sync only).
//   gemm1: M[p] = A[p] @ X  via fp16 mma.m16n8k16, persistent 148 CTAs,
//          384 tiles of 64x256. 512 threads = TWO 8-warp k-split groups:
//          group g handles kt = g (mod 2), private 2-stage smem ring + named
//          barrier; accumulators reduced across groups at tile end.
//   gemm2: out = relu([X|S1|S2] @ [W0|W1|W2]^T + bias)  via tf32 mma.
// ---------------------------------------------------------------------------

#define N_NODES 8192
#define DIM     256
#define NPOW    3

__device__ __align__(1024) float  g_M [(size_t)NPOW * N_NODES * DIM];  // 24 MB
__device__ __align__(1024) __half g_Xh[(size_t)DIM * N_NODES];          // 4 MB [feat][node-perm]

// ---------------- PTX helpers ----------------
__device__ __forceinline__ uint32_t smem_u32(const void* p) {
    return (uint32_t)__cvta_generic_to_shared(p);
}
__device__ __forceinline__ void cp_async16(uint32_t dst, const void* src) {
    asm volatile("cp.async.cg.shared.global [%0], [%1], 16;\n" :: "r"(dst), "l"(src));
}
__device__ __forceinline__ void cp_commit() { asm volatile("cp.async.commit_group;\n"); }
template <int N> __device__ __forceinline__ void cp_wait() {
    asm volatile("cp.async.wait_group %0;\n" :: "n"(N));
}
__device__ __forceinline__ void bar_named(int id, int cnt) {
    asm volatile("bar.sync %0, %1;" :: "r"(id), "r"(cnt) : "memory");
}
__device__ __forceinline__ uint32_t f2tf32(float x) {
    uint32_t r; asm("cvt.rna.tf32.f32 %0, %1;\n" : "=r"(r) : "f"(x)); return r;
}
__device__ __forceinline__ uint32_t lds32(uint32_t a) {
    uint32_t r; asm volatile("ld.shared.b32 %0, [%1];" : "=r"(r) : "r"(a)); return r;
}
__device__ __forceinline__ void lds64(uint32_t& x, uint32_t& y, uint32_t a) {
    asm volatile("ld.shared.v2.b32 {%0,%1}, [%2];" : "=r"(x), "=r"(y) : "r"(a));
}
__device__ __forceinline__ void sts64(uint32_t a, uint32_t x, uint32_t y) {
    asm volatile("st.shared.v2.b32 [%0], {%1,%2};" :: "r"(a), "r"(x), "r"(y));
}
__device__ __forceinline__ void sts128f(uint32_t a, float x, float y, float z, float w) {
    asm volatile("st.shared.v4.f32 [%0], {%1,%2,%3,%4};" :: "r"(a), "f"(x), "f"(y), "f"(z), "f"(w));
}
__device__ __forceinline__ void lds128f(float& x, float& y, float& z, float& w, uint32_t a) {
    asm volatile("ld.shared.v4.f32 {%0,%1,%2,%3}, [%4];" : "=f"(x), "=f"(y), "=f"(z), "=f"(w) : "r"(a));
}
__device__ __forceinline__ void mma_f16(float c[4],
                                        uint32_t a0, uint32_t a1, uint32_t a2, uint32_t a3,
                                        uint32_t b0, uint32_t b1) {
    asm volatile(
        "mma.sync.aligned.m16n8k16.row.col.f32.f16.f16.f32 "
        "{%0,%1,%2,%3}, {%4,%5,%6,%7}, {%8,%9}, {%0,%1,%2,%3};\n"
        : "+f"(c[0]), "+f"(c[1]), "+f"(c[2]), "+f"(c[3])
        : "r"(a0), "r"(a1), "r"(a2), "r"(a3), "r"(b0), "r"(b1));
}
__device__ __forceinline__ void mma_tf32(float c[4],
                                         uint32_t a0, uint32_t a1, uint32_t a2, uint32_t a3,
                                         uint32_t b0, uint32_t b1) {
    asm volatile(
        "mma.sync.aligned.m16n8k8.row.col.f32.tf32.tf32.f32 "
        "{%0,%1,%2,%3}, {%4,%5,%6,%7}, {%8,%9}, {%0,%1,%2,%3};\n"
        : "+f"(c[0]), "+f"(c[1]), "+f"(c[2]), "+f"(c[3])
        : "r"(a0), "r"(a1), "r"(a2), "r"(a3), "r"(b0), "r"(b1));
}
__device__ __forceinline__ uint32_t h2u(__half2 h) {
    return *reinterpret_cast<uint32_t*>(&h);
}

// k-within-16 interleave: positions 4t..4t+3 hold original k {2t,2t+1,2t+8,2t+9}
__device__ __forceinline__ int hperm(int k) {
    return ((k & 7) >> 1) * 4 + ((k >> 3) & 1) * 2 + (k & 1);
}

// ---------------------------------------------------------------------------
// Kernel 0: g_Xh[feat][perm(node)] = fp16_rna(X[node][feat])
// ---------------------------------------------------------------------------
__global__ void __launch_bounds__(256)
prep_xh(const float* __restrict__ X) {
    __shared__ float t[32][33];
    const int n0 = blockIdx.x * 32;
    const int f0 = blockIdx.y * 32;
    const int tx = threadIdx.x, ty = threadIdx.y;
#pragma unroll
    for (int j = 0; j < 32; j += 8)
        t[ty + j][tx] = X[(size_t)(n0 + ty + j) * DIM + f0 + tx];
    __syncthreads();
    const int node = n0 + tx;
    const int ndst = (node & ~15) + hperm(node & 15);
#pragma unroll
    for (int j = 0; j < 32; j += 8)
        g_Xh[(size_t)(f0 + ty + j) * N_NODES + ndst] = __float2half_rn(t[tx][ty + j]);
}

// ---------------------------------------------------------------------------
// Kernel 1: persistent fp16 GEMM, k-split dual-group CTA.
// Tile 64x256, BK=64. Group g (256 threads) does kts g, g+2, ... (64 each).
// Per group: A 2 stages x 64x144B, B 2 stages x 256x160B  -> 100352 B.
// ---------------------------------------------------------------------------
#define A_ROWB    144
#define B_ROWB    160
#define A_STAGEB  (64 * A_ROWB)                   // 9216
#define B_STAGEB  (256 * B_ROWB)                  // 40960
#define GRP_BYTES (2 * A_STAGEB + 2 * B_STAGEB)   // 100352
#define G1_SMEM   (2 * GRP_BYTES + 1024)          // 201728
#define NTG       64
#define TILES     (NPOW * (N_NODES / 64))         // 384
#define GRID1     148

__global__ void __launch_bounds__(512, 1)
volterra_gemm1(const float* __restrict__ A) {
    extern __shared__ char dsm[];
    const uint32_t base = (smem_u32(dsm) + 1023) & ~1023u;

    const int tid   = threadIdx.x;
    const int grp   = tid >> 8;           // 0 or 1
    const int gtid  = tid & 255;
    const int wid_g = gtid >> 5;          // 0..7 within group
    const int lane  = tid & 31;
    const int g     = lane >> 2;
    const int tq    = lane & 3;
    const int rw0   = (wid_g >> 2) * 32;  // 2 row groups of 32
    const int cw0   = (wid_g & 3) * 64;   // 4 col groups of 64

    const int lr0 = gtid >> 4;            // A-load rows: lr0 + 16*i
    const int lk  = (gtid & 15) * 4;

    const uint32_t gbase = base + (uint32_t)grp * GRP_BYTES;
    const uint32_t aSts  = gbase;
    const uint32_t bCp   = gbase + 2 * A_STAGEB;
    const uint32_t aFrag = gbase + (uint32_t)(rw0 + g) * A_ROWB + tq * 4;
    const uint32_t bFrag = bCp + (uint32_t)(cw0 + g) * B_ROWB + tq * 8;
    const int barId = grp + 1;

    for (int t = blockIdx.x; t < TILES; t += GRID1) {
        const int p    = t >> 7;
        const int row0 = (t & 127) * 64;
        const float* Ap = A + (size_t)p * N_NODES * N_NODES;

        float acc[2][8][4];
#pragma unroll
        for (int mt = 0; mt < 2; mt++)
#pragma unroll
            for (int nt = 0; nt < 8; nt++)
#pragma unroll
                for (int i = 0; i < 4; i++) acc[mt][nt][i] = 0.f;

        float4 buf[4];                     // single A staging buffer (regs)

        auto ldgA = [&](int j) {           // load A slab for local iter j
            const int k0 = (2 * j + grp) * 64;
#pragma unroll
            for (int i = 0; i < 4; i++)
                buf[i] = *(const float4*)(Ap + (size_t)(row0 + lr0 + 16 * i) * N_NODES + k0 + lk);
        };
        auto stsA = [&](int j) {           // convert + store into stage j&1
            const uint32_t sa = aSts + (j & 1) * A_STAGEB;
#pragma unroll
            for (int i = 0; i < 4; i++) {
                uint32_t u0 = h2u(__floats2half2_rn(buf[i].x, buf[i].y));
                uint32_t u1 = h2u(__floats2half2_rn(buf[i].z, buf[i].w));
                sts64(sa + (uint32_t)(lr0 + 16 * i) * A_ROWB + (uint32_t)lk * 2, u0, u1);
            }
        };
        auto cpB = [&](int j) {            // async B tile into stage j&1
            const uint32_t sb = bCp + (j & 1) * B_STAGEB;
            const int k0 = (2 * j + grp) * 64;
#pragma unroll
            for (int i = 0; i < 8; i++) {
                int idx = gtid + i * 256;
                int n = idx >> 3, c = idx & 7;
                cp_async16(sb + (uint32_t)n * B_ROWB + c * 16,
                           g_Xh + (size_t)n * N_NODES + k0 + c * 8);
            }
            cp_commit();
        };

        // prologue: A(0) ldg+sts, A(1) ldg into regs, B(0) in flight
        ldgA(0); cpB(0); stsA(0); ldgA(1);

        for (int j = 0; j < NTG; j++) {
            bar_named(barId, 256);               // group done reading stage (j+1)&1
            if (j + 1 < NTG) { cpB(j + 1); stsA(j + 1); }
            if (j + 2 < NTG) ldgA(j + 2);
            if (j + 1 < NTG) cp_wait<1>(); else cp_wait<0>();
            bar_named(barId, 256);               // B(j)/A(j) visible to whole group

            const uint32_t aS = aFrag + (j & 1) * A_STAGEB;
            const uint32_t bS = bFrag + (j & 1) * B_STAGEB;
#pragma unroll
            for (int k16 = 0; k16 < 4; k16++) {
                const uint32_t off = k16 * 32;
                uint32_t a0a = lds32(aS + off);
                uint32_t a1a = lds32(aS + off + 8 * A_ROWB);
                uint32_t a2a = lds32(aS + off + 16);
                uint32_t a3a = lds32(aS + off + 8 * A_ROWB + 16);
                uint32_t a0b = lds32(aS + off + 16 * A_ROWB);
                uint32_t a1b = lds32(aS + off + 24 * A_ROWB);
                uint32_t a2b = lds32(aS + off + 16 * A_ROWB + 16);
                uint32_t a3b = lds32(aS + off + 24 * A_ROWB + 16);
#pragma unroll
                for (int nt = 0; nt < 8; nt++) {
                    uint32_t b0, b1;
                    lds64(b0, b1, bS + nt * 8 * B_ROWB + off);
                    mma_f16(acc[0][nt], a0a, a1a, a2a, a3a, b0, b1);
                    mma_f16(acc[1][nt], a0b, a1b, a2b, a3b, b0, b1);
                }
            }
        }

        // ---- cross-group accumulator reduction + store ----
        const uint32_t red = base + GRP_BYTES + 2 * A_STAGEB;  // group1's B region (80KB >= 64KB)
        __syncthreads();
        if (grp == 1) {
            const uint32_t w = red + (uint32_t)wid_g * 8192 + lane * 16;
#pragma unroll
            for (int mt = 0; mt < 2; mt++)
#pragma unroll
                for (int nt = 0; nt < 8; nt++)
                    sts128f(w + (mt * 8 + nt) * 512,
                            acc[mt][nt][0], acc[mt][nt][1], acc[mt][nt][2], acc[mt][nt][3]);
        }
        __syncthreads();
        if (grp == 0) {
            const uint32_t r = red + (uint32_t)wid_g * 8192 + lane * 16;
            float* Mo = g_M + (size_t)p * N_NODES * DIM;
#pragma unroll
            for (int mt = 0; mt < 2; mt++) {
                const int rr = row0 + rw0 + mt * 16 + g;
#pragma unroll
                for (int nt = 0; nt < 8; nt++) {
                    float x, y, z, w2;
                    lds128f(x, y, z, w2, r + (mt * 8 + nt) * 512);
                    const int c = cw0 + nt * 8 + 2 * tq;
                    *(float2*)&Mo[(size_t)rr * DIM + c] =
                        make_float2(acc[mt][nt][0] + x, acc[mt][nt][1] + y);
                    *(float2*)&Mo[(size_t)(rr + 8) * DIM + c] =
                        make_float2(acc[mt][nt][2] + z, acc[mt][nt][3] + w2);
                }
            }
        }
        __syncthreads();   // red region reused as B stages next tile
    }
}

// ---------------------------------------------------------------------------
// Kernel 2:  out = relu( [X | S1 | S2] @ [W0 | W1 | W2]^T + bias )   (tf32)
// ---------------------------------------------------------------------------
#define TS_STRIDE 36
__global__ void __launch_bounds__(256)
volterra_gemm2(const float* __restrict__ X, const float* __restrict__ W,
               const float* __restrict__ bvec, float* __restrict__ out) {
    __shared__ float Ts[64][TS_STRIDE];
    __shared__ float Ws[128][TS_STRIDE];

    const int row0 = blockIdx.x * 64;
    const int col0 = blockIdx.y * 128;
    const int tid  = threadIdx.x;
    const int wid  = tid >> 5;
    const int lane = tid & 31;
    const int warpRow = (wid >> 2) * 32;
    const int warpCol = (wid & 3) * 32;

    float acc[2][4][4];
#pragma unroll
    for (int mt = 0; mt < 2; mt++)
#pragma unroll
        for (int nt = 0; nt < 4; nt++)
#pragma unroll
            for (int i = 0; i < 4; i++) acc[mt][nt][i] = 0.f;

    const size_t MSZ = (size_t)N_NODES * DIM;

    for (int kc = 0; kc < 24; kc++) {
        const int r  = kc >> 3;
        const int k0 = (kc & 7) * 32;

#pragma unroll
        for (int i = 0; i < 2; i++) {
            int idx = tid + i * 256;
            int rr = idx >> 3, c4 = idx & 7;
            size_t gidx = (size_t)(row0 + rr) * DIM + k0 + c4 * 4;
            float4 v;
            if (r == 0) {
                v = *(const float4*)&X[gidx];
            } else {
                float4 m0 = *(const float4*)&g_M[gidx];
                float4 m1 = *(const float4*)&g_M[MSZ + gidx];
                float4 m2 = *(const float4*)&g_M[2 * MSZ + gidx];
                if (r == 1) {
                    v.x = m0.x + m1.x + m2.x;  v.y = m0.y + m1.y + m2.y;
                    v.z = m0.z + m1.z + m2.z;  v.w = m0.w + m1.w + m2.w;
                } else {
                    float s, q;
                    s = m0.x + m1.x + m2.x; q = m0.x*m0.x + m1.x*m1.x + m2.x*m2.x; v.x = 0.5f*(s*s + q);
                    s = m0.y + m1.y + m2.y; q = m0.y*m0.y + m1.y*m1.y + m2.y*m2.y; v.y = 0.5f*(s*s + q);
                    s = m0.z + m1.z + m2.z; q = m0.z*m0.z + m1.z*m1.z + m2.z*m2.z; v.z = 0.5f*(s*s + q);
                    s = m0.w + m1.w + m2.w; q = m0.w*m0.w + m1.w*m1.w + m2.w*m2.w; v.w = 0.5f*(s*s + q);
                }
            }
            *(float4*)&Ts[rr][c4 * 4] = v;
        }
        const float* Wr = W + (size_t)r * DIM * DIM;
#pragma unroll
        for (int i = 0; i < 4; i++) {
            int idx = tid + i * 256;
            int d = idx >> 3, c4 = idx & 7;
            *(float4*)&Ws[d][c4 * 4] = *(const float4*)&Wr[(size_t)(col0 + d) * DIM + k0 + c4 * 4];
        }
        __syncthreads();

#pragma unroll
        for (int k8 = 0; k8 < 4; k8++) {
            const int kb = k8 * 8;
            uint32_t af[2][4];
#pragma unroll
            for (int mt = 0; mt < 2; mt++) {
                int rr = warpRow + mt * 16 + (lane >> 2);
                int c = kb + (lane & 3);
                af[mt][0] = f2tf32(Ts[rr][c]);
                af[mt][1] = f2tf32(Ts[rr + 8][c]);
                af[mt][2] = f2tf32(Ts[rr][c + 4]);
                af[mt][3] = f2tf32(Ts[rr + 8][c + 4]);
            }
#pragma unroll
            for (int nt = 0; nt < 4; nt++) {
                int d = warpCol + nt * 8 + (lane >> 2);
                int k = kb + (lane & 3);
                uint32_t b0 = f2tf32(Ws[d][k]);
                uint32_t b1 = f2tf32(Ws[d][k + 4]);
                mma_tf32(acc[0][nt], af[0][0], af[0][1], af[0][2], af[0][3], b0, b1);
                mma_tf32(acc[1][nt], af[1][0], af[1][1], af[1][2], af[1][3], b0, b1);
            }
        }
        __syncthreads();
    }

#pragma unroll
    for (int nt = 0; nt < 4; nt++) {
        int c  = col0 + warpCol + nt * 8 + 2 * (lane & 3);
        float bias0 = bvec[c]     + 3.f * bvec[DIM + c]     + 6.f * bvec[2 * DIM + c];
        float bias1 = bvec[c + 1] + 3.f * bvec[DIM + c + 1] + 6.f * bvec[2 * DIM + c + 1];
#pragma unroll
        for (int mt = 0; mt < 2; mt++) {
            int rr = row0 + warpRow + mt * 16 + (lane >> 2);
            float2 v0 = make_float2(fmaxf(acc[mt][nt][0] + bias0, 0.f),
                                    fmaxf(acc[mt][nt][1] + bias1, 0.f));
            float2 v1 = make_float2(fmaxf(acc[mt][nt][2] + bias0, 0.f),
                                    fmaxf(acc[mt][nt][3] + bias1, 0.f));
            *(float2*)&out[(size_t)rr * DIM + c]       = v0;
            *(float2*)&out[(size_t)(rr + 8) * DIM + c] = v1;
        }
    }
}

// ---------------------------------------------------------------------------
extern "C" void kernel_launch(void* const* d_in, const int* in_sizes, int n_in,
                              void* d_out, int out_size) {
    const float *X = nullptr, *A = nullptr, *W = nullptr, *b = nullptr;
    for (int i = 0; i < n_in; i++) {
        long long s = in_sizes[i];
        if      (s == (long long)N_NODES * DIM)            X = (const float*)d_in[i];
        else if (s == (long long)NPOW * N_NODES * N_NODES) A = (const float*)d_in[i];
        else if (s == (long long)NPOW * DIM * DIM)         W = (const float*)d_in[i];
        else if (s == (long long)NPOW * DIM)               b = (const float*)d_in[i];
    }

    cudaFuncSetAttribute(volterra_gemm1,
                         cudaFuncAttributeMaxDynamicSharedMemorySize, G1_SMEM);

    prep_xh<<<dim3(N_NODES / 32, DIM / 32), dim3(32, 8)>>>(X);
    volterra_gemm1<<<GRID1, 512, G1_SMEM>>>(A);
    volterra_gemm2<<<dim3(N_NODES / 64, 2), 256>>>(X, W, b, (float*)d_out);
}